// round 8
// baseline (speedup 1.0000x reference)
#include <cuda_runtime.h>
#include <math.h>
typedef unsigned long long ull;

#define TSTEPS 512
#define HDIM 1024

#define FFMA2(acc,a,b) asm("fma.rn.f32x2 %0, %1, %2, %0;" : "+l"(acc) : "l"(a), "l"(b))
__device__ __forceinline__ float psum(ull v){
    float x, y;
    asm("mov.b64 {%0,%1}, %2;" : "=f"(x), "=f"(y) : "l"(v));
    return x + y;
}

__device__ int g_cnt[4 * TSTEPS];
__global__ void reset_kernel(){
    int i = blockIdx.x * blockDim.x + threadIdx.x;
    if (i < 4 * TSTEPS) g_cnt[i] = 0;
}

// ---------------------------------------------------------------------------
// Phase 1 (unchanged from R7): C = A @ W + b, 128x128 tile, FFMA2 K-paired.
// ---------------------------------------------------------------------------
#define SA 20
__global__ void __launch_bounds__(256, 1) gemm_xw(
    const float* __restrict__ A, const float* __restrict__ W,
    const float* __restrict__ bias, float* __restrict__ C)
{
    __shared__ float sA[2][128 * SA];
    __shared__ float sB[2][8 * 256];
    const int tid = threadIdx.x;
    const int n0 = blockIdx.x * 128, m0 = blockIdx.y * 128;
    const int ty = tid >> 4, tx = tid & 15;
    const int ar = tid >> 1, ah = (tid & 1) * 8;
    const int wn = tid & 127, wk0 = tid >> 7;

    ull acc[8][8];
    #pragma unroll
    for (int i = 0; i < 8; i++)
        #pragma unroll
        for (int j = 0; j < 8; j++) acc[i][j] = 0ull;

    const float* Ap = A + (size_t)(m0 + ar) * HDIM + ah;
    float4 pa0, pa1; float pw[8];
    pa0 = *(const float4*)Ap;
    pa1 = *(const float4*)(Ap + 4);
    #pragma unroll
    for (int q = 0; q < 4; q++) {
        int kp = wk0 + q * 2;
        pw[q*2+0] = W[(size_t)(2*kp+0) * HDIM + n0 + wn];
        pw[q*2+1] = W[(size_t)(2*kp+1) * HDIM + n0 + wn];
    }
    int buf = 0;
    *(float4*)&sA[0][ar*SA + ah] = pa0;
    *(float4*)&sA[0][ar*SA + ah + 4] = pa1;
    #pragma unroll
    for (int q = 0; q < 4; q++) {
        int kp = wk0 + q * 2;
        sB[0][kp*256 + 2*wn]     = pw[q*2+0];
        sB[0][kp*256 + 2*wn + 1] = pw[q*2+1];
    }
    __syncthreads();

    for (int kt = 0; kt < HDIM / 16; kt++) {
        if (kt < HDIM/16 - 1) {
            const float* An = Ap + (kt + 1) * 16;
            pa0 = *(const float4*)An;
            pa1 = *(const float4*)(An + 4);
            #pragma unroll
            for (int q = 0; q < 4; q++) {
                int kp = wk0 + q * 2;
                int k = (kt + 1) * 16 + 2 * kp;
                pw[q*2+0] = W[(size_t)k * HDIM + n0 + wn];
                pw[q*2+1] = W[(size_t)(k+1) * HDIM + n0 + wn];
            }
        }
        const float* cA = sA[buf];
        const float* cB = sB[buf];
        #pragma unroll
        for (int kq = 0; kq < 4; kq++) {
            ull a0[8], a1[8], w0[8], w1[8];
            #pragma unroll
            for (int i = 0; i < 8; i++) {
                ulonglong2 v = *(const ulonglong2*)&cA[(ty + 16*i) * SA + kq*4];
                a0[i] = v.x; a1[i] = v.y;
            }
            #pragma unroll
            for (int j = 0; j < 8; j++) {
                w0[j] = *(const ull*)&cB[(kq*2+0)*256 + 2*(tx + 16*j)];
                w1[j] = *(const ull*)&cB[(kq*2+1)*256 + 2*(tx + 16*j)];
            }
            #pragma unroll
            for (int i = 0; i < 8; i++)
                #pragma unroll
                for (int j = 0; j < 8; j++) {
                    FFMA2(acc[i][j], a0[i], w0[j]);
                    FFMA2(acc[i][j], a1[i], w1[j]);
                }
        }
        if (kt < HDIM/16 - 1) {
            int nb = buf ^ 1;
            *(float4*)&sA[nb][ar*SA + ah] = pa0;
            *(float4*)&sA[nb][ar*SA + ah + 4] = pa1;
            #pragma unroll
            for (int q = 0; q < 4; q++) {
                int kp = wk0 + q * 2;
                sB[nb][kp*256 + 2*wn]     = pw[q*2+0];
                sB[nb][kp*256 + 2*wn + 1] = pw[q*2+1];
            }
        }
        __syncthreads();
        buf ^= 1;
    }
    #pragma unroll
    for (int j = 0; j < 8; j++) {
        float bb = bias[n0 + tx + 16*j];
        #pragma unroll
        for (int i = 0; i < 8; i++)
            C[(size_t)(m0 + ty + 16*i) * HDIM + n0 + tx + 16*j] = psum(acc[i][j]) + bb;
    }
}

// ---------------------------------------------------------------------------
// Phase 2: persistent scan, 128 CTAs (32 cg x 4 rg), 256 threads (8 warps).
// CTA owns 32 rows x 32 cols. Wh slice k-grouped in smem (128KB, loaded once).
// 8-way k-interleaved warp split; warp lanes: lr=lane>>3 (rows), lc=lane&7
// (cols) -> broadcast a-loads (4 addr/warp) and 1-phase w-loads.
// Per-step smem reduction over 8 warp partials, then tanh epilogue.
// ---------------------------------------------------------------------------
#define SHS 132
#define SW_WORDS (256 * 128)
#define SH_WORDS (2 * 32 * SHS)
#define RED_S 36
#define RED_WORDS (8 * 32 * RED_S)
#define SCAN_SMEM ((SW_WORDS + SH_WORDS + RED_WORDS) * 4)

__global__ void __launch_bounds__(256, 1) scan_kernel(
    const float* __restrict__ h0, const float* __restrict__ Wh,
    float* __restrict__ out)
{
    extern __shared__ float sm[];
    float* sW  = sm;                     // [256 kq][32 n][4 k]
    float* sh  = sm + SW_WORDS;          // [2][32 rows][SHS]
    float* red = sh + SH_WORDS;          // [8 w][32 r][RED_S]

    const int tid = threadIdx.x;
    const int w = tid >> 5, lane = tid & 31;
    const int lr = lane >> 3, lc = lane & 7;
    const int cg = blockIdx.x, rg = blockIdx.y, c0 = cg * 32;

    // one-time: Wh slice, k-grouped-by-4 transposed layout
    for (int idx = tid; idx < 32 * HDIM; idx += 256) {
        int k = idx >> 5, n = idx & 31;
        sW[(k >> 2) * 128 + n * 4 + (k & 3)] = Wh[(size_t)k * HDIM + c0 + n];
    }
    __syncthreads();

    const int sr = tid >> 3, sk = (tid & 7) * 16;  // staging map
    const int grow = rg * 32 + sr;
    const int rr = tid >> 3, cb = (tid & 7) * 4;   // epilogue map
    int* cnt = &g_cnt[rg * TSTEPS];

    for (int t = 0; t < TSTEPS; t++) {
        const float* hrow = (t == 0)
            ? h0 + (size_t)grow * HDIM
            : out + ((size_t)grow * TSTEPS + (t - 1)) * HDIM;

        ull acc[8][4];
        #pragma unroll
        for (int i = 0; i < 8; i++)
            #pragma unroll
            for (int j = 0; j < 4; j++) acc[i][j] = 0ull;

        float4 pf[4];
        #pragma unroll
        for (int q = 0; q < 4; q++)
            pf[q] = *(const float4*)&hrow[sk + q * 4];

        int buf = 0;
        for (int c = 0; c < 8; c++) {
            float* dst = sh + buf * (32 * SHS) + sr * SHS + sk;
            #pragma unroll
            for (int q = 0; q < 4; q++)
                *(float4*)&dst[q * 4] = pf[q];
            __syncthreads();
            if (c < 7) {
                const float* src = &hrow[(c + 1) * 128 + sk];
                #pragma unroll
                for (int q = 0; q < 4; q++)
                    pf[q] = *(const float4*)&src[q * 4];
            }
            const float* ch = sh + buf * (32 * SHS);
            #pragma unroll
            for (int u = 0; u < 4; u++) {
                const int kqc = w + 8 * u;                 // kq within chunk
                const float* ap = ch + kqc * 4;
                const float* wp = sW + (c * 32 + kqc) * 128;
                ulonglong2 av[8], wv[4];
                #pragma unroll
                for (int i = 0; i < 8; i++)
                    av[i] = *(const ulonglong2*)&ap[(lr + 4 * i) * SHS];
                #pragma unroll
                for (int j = 0; j < 4; j++)
                    wv[j] = *(const ulonglong2*)&wp[(lc + 8 * j) * 4];
                #pragma unroll
                for (int i = 0; i < 8; i++)
                    #pragma unroll
                    for (int j = 0; j < 4; j++) {
                        FFMA2(acc[i][j], av[i].x, wv[j].x);
                        FFMA2(acc[i][j], av[i].y, wv[j].y);
                    }
            }
            buf ^= 1;
        }

        // write warp partials
        #pragma unroll
        for (int i = 0; i < 8; i++)
            #pragma unroll
            for (int j = 0; j < 4; j++)
                red[w * (32 * RED_S) + (lr + 4 * i) * RED_S + (lc + 8 * j)]
                    = psum(acc[i][j]);
        __syncthreads();

        // reduce 8 partials -> tanh epilogue (4 outputs/thread)
        {
            const int m = rg * 32 + rr;
            float* po = out + ((size_t)m * TSTEPS + t) * HDIM + c0 + cb;
            float4 s = make_float4(0.f, 0.f, 0.f, 0.f);
            #pragma unroll
            for (int ww = 0; ww < 8; ww++) {
                float4 v = *(const float4*)&red[ww * (32 * RED_S) + rr * RED_S + cb];
                s.x += v.x; s.y += v.y; s.z += v.z; s.w += v.w;
            }
            float4 xw = *(const float4*)po;
            float4 o;
            o.x = tanhf(s.x + xw.x);
            o.y = tanhf(s.y + xw.y);
            o.z = tanhf(s.z + xw.z);
            o.w = tanhf(s.w + xw.w);
            *(float4*)po = o;
        }

        if (t < TSTEPS - 1) {
            __threadfence();
            __syncthreads();
            if (tid == 0) {
                atomicAdd(cnt + t, 1);
                while (((volatile int*)cnt)[t] < 32) { }
                __threadfence();
            }
            __syncthreads();
        }
    }
}

extern "C" void kernel_launch(void* const* d_in, const int* in_sizes, int n_in,
                              void* d_out, int out_size) {
    const float* x  = (const float*)d_in[0];
    const float* h0 = (const float*)d_in[1];
    const float* Wx = (const float*)d_in[2];
    const float* Wh = (const float*)d_in[3];
    const float* b  = (const float*)d_in[4];
    float* out = (float*)d_out;

    {
        dim3 grid(HDIM / 128, 65536 / 128);
        gemm_xw<<<grid, 256>>>(x, Wx, b, out);
    }
    reset_kernel<<<4, 512>>>();
    {
        static int done = 0;
        if (!done) {
            cudaFuncSetAttribute(scan_kernel,
                cudaFuncAttributeMaxDynamicSharedMemorySize, SCAN_SMEM);
            done = 1;
        }
        dim3 grid(32, 4);
        scan_kernel<<<grid, 256, SCAN_SMEM>>>(h0, Wh, out);
    }
}